// round 14
// baseline (speedup 1.0000x reference)
#include <cuda_runtime.h>
#include <math.h>

namespace {

constexpr int   NN    = 12;
constexpr int   HID   = 64;
constexpr int   PAD   = 68;    // padded row stride for xl/xr + weight mats (floats)
constexpr int   APAD  = 68;    // padded row stride for xA/xC (floats)
constexpr int   A17   = APAD / 4;  // row stride in 16B units
constexpr float SLOPE = 0.2f;
constexpr float ALPHA = 0.1f;
constexpr int   TPG   = 128;   // threads per graph
constexpr int   NSUB  = 7;     // graphs per block
constexpr int   NTH   = TPG * NSUB;   // 896
constexpr int   NB    = 4096;
constexpr int   GRID  = (NB + NSUB - 1) / NSUB;   // 586

// output section offsets (fp32 elements)
constexpr size_t O1 = 0;
constexpr size_t O2 = 196608;
constexpr size_t OL = 245760;
constexpr size_t OV = 442368;
constexpr size_t OT = 491520;

typedef unsigned long long u64;

__device__ __forceinline__ u64 ffma2(u64 a, u64 b, u64 c)
{
    u64 d;
    asm("fma.rn.f32x2 %0, %1, %2, %3;" : "=l"(d) : "l"(a), "l"(b), "l"(c));
    return d;
}

__device__ __forceinline__ float2 unpack2(u64 v)
{
    float2 f;
    asm("mov.b64 {%0, %1}, %2;" : "=f"(f.x), "=f"(f.y) : "l"(v));
    return f;
}

struct alignas(16) SubS {
    float binp[64];
    float xA  [NN * APAD];    // activations ping (padded rows)
    float xC  [NN * APAD];    // activations pong (x2 persists here)
    float xl  [NN * PAD];
    float xr  [NN * PAD];
    float latent[NN * 4];
    float e   [NN * NN];      // exp(scores); non-adjacent entries stay 0
    short plist[NN * NN];     // compacted list of adjacent pairs
    int   pcnt;
};

struct alignas(16) SM {
    float w_enc1[5 * HID],    b_enc1[HID];
    float w_enc2t[HID * PAD], b_enc2[HID];
    float w_enc3[HID * 3],    b_enc3[4];
    float g_wl1[HID], g_wr1[HID];
    float wl2t[HID * PAD], wr2t[HID * PAD];
    float wl3t[HID * PAD], wr3t[HID * PAD];
    float wl4t[HID * PAD], wr4t[HID * PAD];
    float att1[HID], att2[HID], att3[HID], att4[HID];
    float gb1[HID],  gb2[HID],  gb3[HID],  gb4[HID];
    float w_skip[3 * HID], b_skip[HID];
    float w_lab[HID * 4],  b_lab[4];
    float w_val[HID],      b_val[4];
    SubS  sub[NSUB];
};

__device__ __forceinline__ void barsub(int sb)
{
    asm volatile("bar.sync %0, %1;" :: "r"(sb + 1), "n"(TPG) : "memory");
}

__device__ __forceinline__ float lrelu(float v) { return fmaxf(v, SLOPE * v); }

// single 64x64 GEMM + bias + relu; pair-shared weight column:
// thread = (hc = tid>>1, rb = (tid&1)*6); 6 rows each, column read once per pair.
__device__ __forceinline__ void gemm64_relu6p(const float* __restrict__ X,
                                              const float* __restrict__ Wt,
                                              const float* __restrict__ bias,
                                              float* __restrict__ Y, int hc, int rb)
{
    u64 acc[6];
#pragma unroll
    for (int r = 0; r < 6; ++r) acc[r] = 0ull;
    const ulonglong2* Wp = (const ulonglong2*)(Wt + hc * PAD);
    const ulonglong2* X4 = (const ulonglong2*)X;
#pragma unroll
    for (int k4 = 0; k4 < 16; ++k4) {
        ulonglong2 w = Wp[k4];
#pragma unroll
        for (int r = 0; r < 6; ++r) {
            ulonglong2 x = X4[(rb + r) * A17 + k4];
            acc[r] = ffma2(x.x, w.x, acc[r]);
            acc[r] = ffma2(x.y, w.y, acc[r]);
        }
    }
    const float bv = bias[hc];
#pragma unroll
    for (int r = 0; r < 6; ++r) {
        float2 f = unpack2(acc[r]);
        Y[(rb + r) * APAD + hc] = fmaxf(bv + (f.x + f.y), 0.f);
    }
}

// dual 64x64 GEMM (no bias), pair-shared weight columns; outputs stride PAD
__device__ __forceinline__ void dual_gemm6p(const float* __restrict__ X,
                                            const float* __restrict__ WLt,
                                            const float* __restrict__ WRt,
                                            float* __restrict__ XL,
                                            float* __restrict__ XR, int hc, int rb)
{
    u64 accL[6], accR[6];
#pragma unroll
    for (int r = 0; r < 6; ++r) { accL[r] = 0ull; accR[r] = 0ull; }
    const ulonglong2* Lp = (const ulonglong2*)(WLt + hc * PAD);
    const ulonglong2* Rp = (const ulonglong2*)(WRt + hc * PAD);
    const ulonglong2* X4 = (const ulonglong2*)X;
#pragma unroll
    for (int k4 = 0; k4 < 16; ++k4) {
        ulonglong2 wl = Lp[k4];
        ulonglong2 wr = Rp[k4];
#pragma unroll
        for (int r = 0; r < 6; ++r) {
            ulonglong2 x = X4[(rb + r) * A17 + k4];
            accL[r] = ffma2(x.x, wl.x, accL[r]);
            accL[r] = ffma2(x.y, wl.y, accL[r]);
            accR[r] = ffma2(x.x, wr.x, accR[r]);
            accR[r] = ffma2(x.y, wr.y, accR[r]);
        }
    }
#pragma unroll
    for (int r = 0; r < 6; ++r) {
        float2 fl = unpack2(accL[r]);
        float2 fr = unpack2(accR[r]);
        XL[(rb + r) * PAD + hc] = fl.x + fl.y;
        XR[(rb + r) * PAD + hc] = fr.x + fr.y;
    }
}

// attention scores over COMPACTED pair list, k-split across lane pairs:
// thread = (pair t = idx>>1, k-half = idx&1); partial dot combined via shfl.
__device__ __forceinline__ void gat_scores(SubS& s, const float* __restrict__ attv,
                                           int tid)
{
    const int cnt2 = 2 * s.pcnt;
    for (int base = 0; base < cnt2; base += TPG) {
        const int idx = base + tid;
        const bool act = idx < cnt2;
        const int t = act ? (idx >> 1) : 0;
        const int half = idx & 1;
        const int p = s.plist[t];
        const int i = p / NN, j = p - (p / NN) * NN;
        const float4* xlj = (const float4*)(s.xl + j * PAD) + half * 8;
        const float4* xri = (const float4*)(s.xr + i * PAD) + half * 8;
        const float4* at4 = (const float4*)attv + half * 8;
        float a0 = 0.f, a1 = 0.f;
#pragma unroll
        for (int k = 0; k < 8; k += 2) {
            float4 l0 = xlj[k],     r0 = xri[k],     w0 = at4[k];
            float4 l1 = xlj[k + 1], r1 = xri[k + 1], w1 = at4[k + 1];
            a0 = fmaf(lrelu(l0.x + r0.x), w0.x, a0);
            a0 = fmaf(lrelu(l0.y + r0.y), w0.y, a0);
            a0 = fmaf(lrelu(l0.z + r0.z), w0.z, a0);
            a0 = fmaf(lrelu(l0.w + r0.w), w0.w, a0);
            a1 = fmaf(lrelu(l1.x + r1.x), w1.x, a1);
            a1 = fmaf(lrelu(l1.y + r1.y), w1.y, a1);
            a1 = fmaf(lrelu(l1.z + r1.z), w1.z, a1);
            a1 = fmaf(lrelu(l1.w + r1.w), w1.w, a1);
        }
        float a = a0 + a1;
        a += __shfl_xor_sync(0xFFFFFFFFu, a, 1);
        if (act && half == 0) s.e[p] = __expf(a);
    }
}

// GAT1 scores: xl/xr are rank-1 (x0[n]*wl[h], x0[n]*wr[h]); read shared wl/wr/att
// (broadcast, shared by every graph) + 2 scalars instead of per-graph xl/xr rows.
__device__ __forceinline__ void gat1_scores(SubS& s,
                                            const float* __restrict__ wl1,
                                            const float* __restrict__ wr1,
                                            const float* __restrict__ attv,
                                            int tid)
{
    const int cnt2 = 2 * s.pcnt;
    for (int base = 0; base < cnt2; base += TPG) {
        const int idx = base + tid;
        const bool act = idx < cnt2;
        const int t = act ? (idx >> 1) : 0;
        const int half = idx & 1;
        const int p = s.plist[t];
        const int i = p / NN, j = p - (p / NN) * NN;
        const float x0j = s.latent[j * 4 + 2];
        const float x0i = s.latent[i * 4 + 2];
        const float4* wl4 = (const float4*)wl1 + half * 8;
        const float4* wr4 = (const float4*)wr1 + half * 8;
        const float4* at4 = (const float4*)attv + half * 8;
        float a0 = 0.f, a1 = 0.f;
#pragma unroll
        for (int k = 0; k < 8; k += 2) {
            float4 l0 = wl4[k],     r0 = wr4[k],     w0 = at4[k];
            float4 l1 = wl4[k + 1], r1 = wr4[k + 1], w1 = at4[k + 1];
            a0 = fmaf(lrelu(x0j * l0.x + x0i * r0.x), w0.x, a0);
            a0 = fmaf(lrelu(x0j * l0.y + x0i * r0.y), w0.y, a0);
            a0 = fmaf(lrelu(x0j * l0.z + x0i * r0.z), w0.z, a0);
            a0 = fmaf(lrelu(x0j * l0.w + x0i * r0.w), w0.w, a0);
            a1 = fmaf(lrelu(x0j * l1.x + x0i * r1.x), w1.x, a1);
            a1 = fmaf(lrelu(x0j * l1.y + x0i * r1.y), w1.y, a1);
            a1 = fmaf(lrelu(x0j * l1.z + x0i * r1.z), w1.z, a1);
            a1 = fmaf(lrelu(x0j * l1.w + x0i * r1.w), w1.w, a1);
        }
        float a = a0 + a1;
        a += __shfl_xor_sync(0xFFFFFFFFu, a, 1);
        if (act && half == 0) s.e[p] = __expf(a);
    }
}

// GAT1 aggregation, factorized: out[n,h] = relu( wl[h]*(sum_j e[n,j]*x0[j])/rs + b[h] )
__device__ __forceinline__ void gat1_agg(SubS& s,
                                         const float* __restrict__ wl1,
                                         const float* __restrict__ bias,
                                         float* __restrict__ xout, int h, int gg)
{
    const int nb = gg * 6;
    float x0v[NN];
#pragma unroll
    for (int j = 0; j < NN; ++j) x0v[j] = s.latent[j * 4 + 2];
    const float wlh = wl1[h];
    const float bv  = bias[h];
#pragma unroll
    for (int r = 0; r < 6; ++r) {
        const float4* e4 = (const float4*)(s.e + (nb + r) * NN);
        float4 e0 = e4[0], e1 = e4[1], e2 = e4[2];
        float rs = ((e0.x + e0.y) + (e0.z + e0.w))
                 + ((e1.x + e1.y) + (e1.z + e1.w))
                 + ((e2.x + e2.y) + (e2.z + e2.w));
        float t = 0.f;
        t = fmaf(e0.x, x0v[0], t);  t = fmaf(e0.y, x0v[1], t);
        t = fmaf(e0.z, x0v[2], t);  t = fmaf(e0.w, x0v[3], t);
        t = fmaf(e1.x, x0v[4], t);  t = fmaf(e1.y, x0v[5], t);
        t = fmaf(e1.z, x0v[6], t);  t = fmaf(e1.w, x0v[7], t);
        t = fmaf(e2.x, x0v[8], t);  t = fmaf(e2.y, x0v[9], t);
        t = fmaf(e2.z, x0v[10], t); t = fmaf(e2.w, x0v[11], t);
        float a = fmaf(wlh * t, __frcp_rn(rs), bv);
        xout[(nb + r) * APAD + h] = fmaxf(a, 0.f);
    }
}

// out[n,h] = relu( (sum_j e[n,j]*xl[j,h]) / rowsum + bias [+ alpha*skip] ), 6 rows/thread
__device__ __forceinline__ void gat_agg6(SubS& s, const float* __restrict__ bias,
                                         float* __restrict__ xout, int h, int gg,
                                         const float* skipreg, int mode)
{
    const int nb = gg * 6;
    float xv[NN];
#pragma unroll
    for (int j = 0; j < NN; ++j) xv[j] = s.xl[j * PAD + h];
    const float bv = bias[h];
#pragma unroll
    for (int r = 0; r < 6; ++r) {
        const float4* e4 = (const float4*)(s.e + (nb + r) * NN);
        float4 e0 = e4[0], e1 = e4[1], e2 = e4[2];
        float rs = ((e0.x + e0.y) + (e0.z + e0.w))
                 + ((e1.x + e1.y) + (e1.z + e1.w))
                 + ((e2.x + e2.y) + (e2.z + e2.w));
        float a = 0.f;
        a = fmaf(e0.x, xv[0], a);  a = fmaf(e0.y, xv[1], a);
        a = fmaf(e0.z, xv[2], a);  a = fmaf(e0.w, xv[3], a);
        a = fmaf(e1.x, xv[4], a);  a = fmaf(e1.y, xv[5], a);
        a = fmaf(e1.z, xv[6], a);  a = fmaf(e1.w, xv[7], a);
        a = fmaf(e2.x, xv[8], a);  a = fmaf(e2.y, xv[9], a);
        a = fmaf(e2.z, xv[10], a); a = fmaf(e2.w, xv[11], a);
        a = fmaf(a, __frcp_rn(rs), bv);
        if (mode == 1) a += ALPHA * skipreg[r];
        xout[(nb + r) * APAD + h] = fmaxf(a, 0.f);
    }
}

// Gabriel adjacency for pair p (symmetric); latent in smem
__device__ __forceinline__ int gabriel_adj(const SubS& s, int p)
{
    const int i = p / NN, j = p - (p / NN) * NN;
    if (i == j) return 1;
    float xi = s.latent[i * 4], yi = s.latent[i * 4 + 1];
    float xj = s.latent[j * 4], yj = s.latent[j * 4 + 1];
    float dx = xi - xj, dy = yi - yj;
    float r2 = (dx * dx + dy * dy) * 0.25f;
    float mx = (xi + xj) * 0.5f, my = (yi + yj) * 0.5f;
    int ok = 1;
#pragma unroll
    for (int k = 0; k < NN; ++k) {
        if (k == i || k == j) continue;
        float ax = s.latent[k * 4] - mx;
        float ay = s.latent[k * 4 + 1] - my;
        float d2 = ax * ax + ay * ay;
        ok &= (d2 > r2) ? 1 : 0;
    }
    return ok;
}

__global__ void __launch_bounds__(NTH, 1)
gae_kernel(const float* __restrict__ batch,
           const float* __restrict__ enc_w1, const float* __restrict__ enc_b1,
           const float* __restrict__ enc_w2, const float* __restrict__ enc_b2,
           const float* __restrict__ enc_w3, const float* __restrict__ enc_b3,
           const float* __restrict__ g1_wl, const float* __restrict__ g1_wr,
           const float* __restrict__ g1_att, const float* __restrict__ g1_b,
           const float* __restrict__ g2_wl, const float* __restrict__ g2_wr,
           const float* __restrict__ g2_att, const float* __restrict__ g2_b,
           const float* __restrict__ g3_wl, const float* __restrict__ g3_wr,
           const float* __restrict__ g3_att, const float* __restrict__ g3_b,
           const float* __restrict__ g4_wl, const float* __restrict__ g4_wr,
           const float* __restrict__ g4_att, const float* __restrict__ g4_b,
           const float* __restrict__ lab_w, const float* __restrict__ lab_b,
           const float* __restrict__ val_w, const float* __restrict__ val_b,
           const float* __restrict__ skip_w, const float* __restrict__ skip_b,
           float* __restrict__ out)
{
    extern __shared__ unsigned char smraw[];
    SM& S = *reinterpret_cast<SM*>(smraw);
    const int T = threadIdx.x;

    // ---- stage weights (strided loops) ----
    for (int i = T; i < HID * HID; i += NTH) {
        const int k = i >> 6, hh = i & 63;
        const int d = hh * PAD + k;
        S.w_enc2t[d] = enc_w2[i];
        S.wl2t[d] = g2_wl[i]; S.wr2t[d] = g2_wr[i];
        S.wl3t[d] = g3_wl[i]; S.wr3t[d] = g3_wr[i];
        S.wl4t[d] = g4_wl[i]; S.wr4t[d] = g4_wr[i];
    }
    for (int i = T; i < 5 * HID; i += NTH) S.w_enc1[i] = enc_w1[i];
    for (int i = T; i < 4 * HID; i += NTH) S.w_lab[i] = lab_w[i];
    for (int i = T; i < 3 * HID; i += NTH) { S.w_enc3[i] = enc_w3[i]; S.w_skip[i] = skip_w[i]; }
    if (T < HID) {
        const int i = T;
        S.b_enc1[i] = enc_b1[i]; S.b_enc2[i] = enc_b2[i];
        S.g_wl1[i] = g1_wl[i];   S.g_wr1[i] = g1_wr[i];
        S.att1[i] = g1_att[i];   S.gb1[i] = g1_b[i];
        S.att2[i] = g2_att[i];   S.gb2[i] = g2_b[i];
        S.att3[i] = g3_att[i];   S.gb3[i] = g3_b[i];
        S.att4[i] = g4_att[i];   S.gb4[i] = g4_b[i];
        S.b_skip[i] = skip_b[i]; S.w_val[i] = val_w[i];
    } else if (T >= 64 && T < 67) {
        S.b_enc3[T - 64] = enc_b3[T - 64];
    } else if (T >= 68 && T < 72) {
        S.b_lab[T - 68] = lab_b[T - 68];
    } else if (T == 72) {
        S.b_val[0] = val_b[0];
    }
    __syncthreads();

    const int sb  = T / TPG;
    const int tid = T - sb * TPG;   // 0..127
    SubS& s = S.sub[sb];
    const int h  = tid & 63;        // mapping A (attn/agg/proj/heads)
    const int gg = tid >> 6;        // 0 or 1
    const int nb = gg * 6;
    const int hc = tid >> 1;        // mapping B (pair-shared GEMMs): column
    const int rb = (tid & 1) * 6;   //   row base (even: 0-5, odd: 6-11)
    const int b = blockIdx.x * NSUB + sb;
    const bool active = (b < NB);

    // ---- input + passthrough; reset pair counter ----
    if (tid == 127) s.pcnt = 0;
    if (active && tid < 60) {
        float v = batch[(size_t)b * 60 + tid];
        s.binp[tid] = v;
        int n = tid / 5, c = tid - n * 5;
        if (c < 4) out[O1 + (size_t)b * 48 + n * 4 + c] = v;
        else       out[O2 + (size_t)b * 12 + n] = v;
    }
    barsub(sb);

    // ---- encoder layer 1 (K=5) -> xA ----
    {
        float a[6];
        const float bv = S.b_enc1[h];
#pragma unroll
        for (int r = 0; r < 6; ++r) a[r] = bv;
#pragma unroll
        for (int k = 0; k < 5; ++k) {
            float w = S.w_enc1[k * HID + h];
#pragma unroll
            for (int r = 0; r < 6; ++r)
                a[r] = fmaf(s.binp[(nb + r) * 5 + k], w, a[r]);
        }
#pragma unroll
        for (int r = 0; r < 6; ++r) s.xA[(nb + r) * APAD + h] = fmaxf(a[r], 0.f);
    }
    barsub(sb);

    // ---- encoder layer 2 -> xC (pair-shared) ----
    gemm64_relu6p(s.xA, S.w_enc2t, S.b_enc2, s.xC, hc, rb);
    barsub(sb);

    // ---- latent (64->3), k-split across lane pairs; 72 writers ----
    {
        const int t    = tid >> 1;
        const int half = tid & 1;
        const int tt   = (t < 36) ? t : 0;
        const int n    = tt / 3, c = tt - n * 3;
        float a = 0.f;
#pragma unroll
        for (int kk = 0; kk < 32; ++kk) {
            const int k = half * 32 + kk;
            a = fmaf(s.xC[n * APAD + k], S.w_enc3[k * 3 + c], a);
        }
        a += __shfl_xor_sync(0xFFFFFFFFu, a, 1);
        if (t < 36 && half == 0) {
            a += S.b_enc3[c];
            s.latent[n * 4 + c] = a;
            if (active) out[OT + (size_t)b * 36 + n * 3 + c] = a;
        }
    }
    barsub(sb);

    // ---- adjacency -> compacted pair list; zero e; skip(reg) ----
    s.e[tid] = 0.0f;
    if (tid < 16) s.e[128 + tid] = 0.0f;
    {
        int adj0 = gabriel_adj(s, tid);
        if (adj0) {
            int k = atomicAdd(&s.pcnt, 1);
            s.plist[k] = (short)tid;
        }
        if (tid < 16) {
            int adj1 = gabriel_adj(s, tid + 128);
            if (adj1) {
                int k = atomicAdd(&s.pcnt, 1);
                s.plist[k] = (short)(tid + 128);
            }
        }
    }
    float skipreg[6];
    {
        const float bv = S.b_skip[h];
#pragma unroll
        for (int r = 0; r < 6; ++r) skipreg[r] = bv;
#pragma unroll
        for (int c = 0; c < 3; ++c) {
            float w = S.w_skip[c * HID + h];
#pragma unroll
            for (int r = 0; r < 6; ++r)
                skipreg[r] = fmaf(s.latent[(nb + r) * 4 + c], w, skipreg[r]);
        }
    }
    barsub(sb);

    // ---- GAT 1 -> xA (x1); rank-1 fast path (no projection phase) ----
    gat1_scores(s, S.g_wl1, S.g_wr1, S.att1, tid);
    barsub(sb);
    gat1_agg(s, S.g_wl1, S.gb1, s.xA, h, gg);
    barsub(sb);

    // ---- GAT 2 -> xC (x2) ----
    dual_gemm6p(s.xA, S.wl2t, S.wr2t, s.xl, s.xr, hc, rb);
    barsub(sb);
    gat_scores(s, S.att2, tid);
    barsub(sb);
    gat_agg6(s, S.gb2, s.xC, h, gg, skipreg, 0);
    barsub(sb);

    // ---- GAT 3 -> xA (x3) ----
    dual_gemm6p(s.xC, S.wl3t, S.wr3t, s.xl, s.xr, hc, rb);
    barsub(sb);
    gat_scores(s, S.att3, tid);
    barsub(sb);
    gat_agg6(s, S.gb3, s.xA, h, gg, skipreg, 1);
    barsub(sb);

    // ---- GAT 4 projections (reads xC = x2) + logits head (reads xA = x3, k-split) ----
    dual_gemm6p(s.xC, S.wl4t, S.wr4t, s.xl, s.xr, hc, rb);
    {
        const int t    = tid >> 1;
        const int half = tid & 1;
        if (t < 48) {   // warps 0-2 fully active; warp 3 skips (warp-aligned)
            const int n = t / 4, c = t - n * 4;
            float a = 0.f;
#pragma unroll
            for (int kk = 0; kk < 32; ++kk) {
                const int k = half * 32 + kk;
                a = fmaf(s.xA[n * APAD + k], S.w_lab[k * 4 + c], a);
            }
            a += __shfl_xor_sync(0xFFFFFFFFu, a, 1);
            if (active && half == 0)
                out[OL + (size_t)b * 48 + n * 4 + c] = a + S.b_lab[c];
        }
    }
    barsub(sb);

    // ---- GAT 4 -> xA (x4) ----
    gat_scores(s, S.att4, tid);
    barsub(sb);
    gat_agg6(s, S.gb4, s.xA, h, gg, skipreg, 1);
    barsub(sb);

    // ---- values head (k-split, warp 0 only) ----
    if (tid < 32) {
        const int t    = tid >> 1;
        const int half = tid & 1;
        const int n    = (t < NN) ? t : 0;
        float a = 0.f;
#pragma unroll
        for (int kk = 0; kk < 32; ++kk) {
            const int k = half * 32 + kk;
            a = fmaf(s.xA[n * APAD + k], S.w_val[k], a);
        }
        a += __shfl_xor_sync(0xFFFFFFFFu, a, 1);
        if (active && t < NN && half == 0)
            out[OV + (size_t)b * 12 + n] = a + S.b_val[0];
    }
}

} // anonymous namespace

extern "C" void kernel_launch(void* const* d_in, const int* in_sizes, int n_in,
                              void* d_out, int out_size)
{
    const float* p[29];
    for (int i = 0; i < 29; ++i) p[i] = (const float*)d_in[i];
    float* out = (float*)d_out;

    cudaFuncSetAttribute(gae_kernel, cudaFuncAttributeMaxDynamicSharedMemorySize,
                         (int)sizeof(SM));

    gae_kernel<<<GRID, NTH, sizeof(SM)>>>(
        p[0],
        p[1], p[2], p[3], p[4], p[5], p[6],
        p[7], p[8], p[9], p[10],
        p[11], p[12], p[13], p[14],
        p[15], p[16], p[17], p[18],
        p[19], p[20], p[21], p[22],
        p[23], p[24], p[25], p[26], p[27], p[28],
        out);
}

// round 15
// speedup vs baseline: 1.2177x; 1.2177x over previous
#include <cuda_runtime.h>
#include <math.h>

namespace {

constexpr int   NN    = 12;
constexpr int   HID   = 64;
constexpr int   PAD   = 68;    // padded row stride for xl/xr + weight mats (floats)
constexpr int   APAD  = 68;    // padded row stride for xA/xC (floats)
constexpr int   A17   = APAD / 4;  // row stride in 16B units
constexpr float SLOPE = 0.2f;
constexpr float ALPHA = 0.1f;
constexpr int   TPG   = 128;   // threads per graph
constexpr int   NSUB  = 7;     // graphs per block per iteration
constexpr int   NTH   = TPG * NSUB;   // 896
constexpr int   NB    = 4096;
constexpr int   GRIDP = 148;   // persistent: one block per SM
constexpr int   ITERS = (NB + GRIDP * NSUB - 1) / (GRIDP * NSUB);  // 4

// output section offsets (fp32 elements)
constexpr size_t O1 = 0;
constexpr size_t O2 = 196608;
constexpr size_t OL = 245760;
constexpr size_t OV = 442368;
constexpr size_t OT = 491520;

typedef unsigned long long u64;

__device__ __forceinline__ u64 ffma2(u64 a, u64 b, u64 c)
{
    u64 d;
    asm("fma.rn.f32x2 %0, %1, %2, %3;" : "=l"(d) : "l"(a), "l"(b), "l"(c));
    return d;
}

__device__ __forceinline__ float2 unpack2(u64 v)
{
    float2 f;
    asm("mov.b64 {%0, %1}, %2;" : "=f"(f.x), "=f"(f.y) : "l"(v));
    return f;
}

struct alignas(16) SubS {
    float binp[64];
    float xA  [NN * APAD];    // activations ping (padded rows)
    float xC  [NN * APAD];    // activations pong (x2 persists here)
    float xl  [NN * PAD];
    float xr  [NN * PAD];
    float latent[NN * 4];
    float e   [NN * NN];      // exp(scores); non-adjacent entries stay 0
    short plist[NN * NN];     // compacted list of adjacent pairs
    int   pcnt;
};

struct alignas(16) SM {
    float w_enc1[5 * HID],    b_enc1[HID];
    float w_enc2t[HID * PAD], b_enc2[HID];
    float w_enc3[HID * 3],    b_enc3[4];
    float g_wl1[HID], g_wr1[HID];
    float wl2t[HID * PAD], wr2t[HID * PAD];
    float wl3t[HID * PAD], wr3t[HID * PAD];
    float wl4t[HID * PAD], wr4t[HID * PAD];
    float att1[HID], att2[HID], att3[HID], att4[HID];
    float gb1[HID],  gb2[HID],  gb3[HID],  gb4[HID];
    float w_skip[3 * HID], b_skip[HID];
    float w_lab[HID * 4],  b_lab[4];
    float w_val[HID],      b_val[4];
    SubS  sub[NSUB];
};

__device__ __forceinline__ void barsub(int sb)
{
    asm volatile("bar.sync %0, %1;" :: "r"(sb + 1), "n"(TPG) : "memory");
}

__device__ __forceinline__ float lrelu(float v) { return fmaxf(v, SLOPE * v); }

// single 64x64 GEMM + bias + relu; pair-shared weight column:
// thread = (hc = tid>>1, rb = (tid&1)*6); 6 rows each, column read once per pair.
__device__ __forceinline__ void gemm64_relu6p(const float* __restrict__ X,
                                              const float* __restrict__ Wt,
                                              const float* __restrict__ bias,
                                              float* __restrict__ Y, int hc, int rb)
{
    u64 acc[6];
#pragma unroll
    for (int r = 0; r < 6; ++r) acc[r] = 0ull;
    const ulonglong2* Wp = (const ulonglong2*)(Wt + hc * PAD);
    const ulonglong2* X4 = (const ulonglong2*)X;
#pragma unroll
    for (int k4 = 0; k4 < 16; ++k4) {
        ulonglong2 w = Wp[k4];
#pragma unroll
        for (int r = 0; r < 6; ++r) {
            ulonglong2 x = X4[(rb + r) * A17 + k4];
            acc[r] = ffma2(x.x, w.x, acc[r]);
            acc[r] = ffma2(x.y, w.y, acc[r]);
        }
    }
    const float bv = bias[hc];
#pragma unroll
    for (int r = 0; r < 6; ++r) {
        float2 f = unpack2(acc[r]);
        Y[(rb + r) * APAD + hc] = fmaxf(bv + (f.x + f.y), 0.f);
    }
}

// dual 64x64 GEMM (no bias), pair-shared weight columns; outputs stride PAD
__device__ __forceinline__ void dual_gemm6p(const float* __restrict__ X,
                                            const float* __restrict__ WLt,
                                            const float* __restrict__ WRt,
                                            float* __restrict__ XL,
                                            float* __restrict__ XR, int hc, int rb)
{
    u64 accL[6], accR[6];
#pragma unroll
    for (int r = 0; r < 6; ++r) { accL[r] = 0ull; accR[r] = 0ull; }
    const ulonglong2* Lp = (const ulonglong2*)(WLt + hc * PAD);
    const ulonglong2* Rp = (const ulonglong2*)(WRt + hc * PAD);
    const ulonglong2* X4 = (const ulonglong2*)X;
#pragma unroll
    for (int k4 = 0; k4 < 16; ++k4) {
        ulonglong2 wl = Lp[k4];
        ulonglong2 wr = Rp[k4];
#pragma unroll
        for (int r = 0; r < 6; ++r) {
            ulonglong2 x = X4[(rb + r) * A17 + k4];
            accL[r] = ffma2(x.x, wl.x, accL[r]);
            accL[r] = ffma2(x.y, wl.y, accL[r]);
            accR[r] = ffma2(x.x, wr.x, accR[r]);
            accR[r] = ffma2(x.y, wr.y, accR[r]);
        }
    }
#pragma unroll
    for (int r = 0; r < 6; ++r) {
        float2 fl = unpack2(accL[r]);
        float2 fr = unpack2(accR[r]);
        XL[(rb + r) * PAD + hc] = fl.x + fl.y;
        XR[(rb + r) * PAD + hc] = fr.x + fr.y;
    }
}

// attention scores over COMPACTED pair list, k-split across lane pairs:
// thread = (pair t = idx>>1, k-half = idx&1); partial dot combined via shfl.
__device__ __forceinline__ void gat_scores(SubS& s, const float* __restrict__ attv,
                                           int tid)
{
    const int cnt2 = 2 * s.pcnt;
    for (int base = 0; base < cnt2; base += TPG) {
        const int idx = base + tid;
        const bool act = idx < cnt2;
        const int t = act ? (idx >> 1) : 0;
        const int half = idx & 1;
        const int p = s.plist[t];
        const int i = p / NN, j = p - (p / NN) * NN;
        const float4* xlj = (const float4*)(s.xl + j * PAD) + half * 8;
        const float4* xri = (const float4*)(s.xr + i * PAD) + half * 8;
        const float4* at4 = (const float4*)attv + half * 8;
        float a0 = 0.f, a1 = 0.f;
#pragma unroll
        for (int k = 0; k < 8; k += 2) {
            float4 l0 = xlj[k],     r0 = xri[k],     w0 = at4[k];
            float4 l1 = xlj[k + 1], r1 = xri[k + 1], w1 = at4[k + 1];
            a0 = fmaf(lrelu(l0.x + r0.x), w0.x, a0);
            a0 = fmaf(lrelu(l0.y + r0.y), w0.y, a0);
            a0 = fmaf(lrelu(l0.z + r0.z), w0.z, a0);
            a0 = fmaf(lrelu(l0.w + r0.w), w0.w, a0);
            a1 = fmaf(lrelu(l1.x + r1.x), w1.x, a1);
            a1 = fmaf(lrelu(l1.y + r1.y), w1.y, a1);
            a1 = fmaf(lrelu(l1.z + r1.z), w1.z, a1);
            a1 = fmaf(lrelu(l1.w + r1.w), w1.w, a1);
        }
        float a = a0 + a1;
        a += __shfl_xor_sync(0xFFFFFFFFu, a, 1);
        if (act && half == 0) s.e[p] = __expf(a);
    }
}

// out[n,h] = relu( (sum_j e[n,j]*xl[j,h]) / rowsum + bias [+ alpha*skip] ), 6 rows/thread
__device__ __forceinline__ void gat_agg6(SubS& s, const float* __restrict__ bias,
                                         float* __restrict__ xout, int h, int gg,
                                         const float* skipreg, int mode)
{
    const int nb = gg * 6;
    float xv[NN];
#pragma unroll
    for (int j = 0; j < NN; ++j) xv[j] = s.xl[j * PAD + h];
    const float bv = bias[h];
#pragma unroll
    for (int r = 0; r < 6; ++r) {
        const float4* e4 = (const float4*)(s.e + (nb + r) * NN);
        float4 e0 = e4[0], e1 = e4[1], e2 = e4[2];
        float rs = ((e0.x + e0.y) + (e0.z + e0.w))
                 + ((e1.x + e1.y) + (e1.z + e1.w))
                 + ((e2.x + e2.y) + (e2.z + e2.w));
        float a = 0.f;
        a = fmaf(e0.x, xv[0], a);  a = fmaf(e0.y, xv[1], a);
        a = fmaf(e0.z, xv[2], a);  a = fmaf(e0.w, xv[3], a);
        a = fmaf(e1.x, xv[4], a);  a = fmaf(e1.y, xv[5], a);
        a = fmaf(e1.z, xv[6], a);  a = fmaf(e1.w, xv[7], a);
        a = fmaf(e2.x, xv[8], a);  a = fmaf(e2.y, xv[9], a);
        a = fmaf(e2.z, xv[10], a); a = fmaf(e2.w, xv[11], a);
        a = fmaf(a, __frcp_rn(rs), bv);
        if (mode == 1) a += ALPHA * skipreg[r];
        xout[(nb + r) * APAD + h] = fmaxf(a, 0.f);
    }
}

// Gabriel adjacency for pair p (symmetric); latent in smem
__device__ __forceinline__ int gabriel_adj(const SubS& s, int p)
{
    const int i = p / NN, j = p - (p / NN) * NN;
    if (i == j) return 1;
    float xi = s.latent[i * 4], yi = s.latent[i * 4 + 1];
    float xj = s.latent[j * 4], yj = s.latent[j * 4 + 1];
    float dx = xi - xj, dy = yi - yj;
    float r2 = (dx * dx + dy * dy) * 0.25f;
    float mx = (xi + xj) * 0.5f, my = (yi + yj) * 0.5f;
    int ok = 1;
#pragma unroll
    for (int k = 0; k < NN; ++k) {
        if (k == i || k == j) continue;
        float ax = s.latent[k * 4] - mx;
        float ay = s.latent[k * 4 + 1] - my;
        float d2 = ax * ax + ay * ay;
        ok &= (d2 > r2) ? 1 : 0;
    }
    return ok;
}

__global__ void __launch_bounds__(NTH, 1)
gae_kernel(const float* __restrict__ batch,
           const float* __restrict__ enc_w1, const float* __restrict__ enc_b1,
           const float* __restrict__ enc_w2, const float* __restrict__ enc_b2,
           const float* __restrict__ enc_w3, const float* __restrict__ enc_b3,
           const float* __restrict__ g1_wl, const float* __restrict__ g1_wr,
           const float* __restrict__ g1_att, const float* __restrict__ g1_b,
           const float* __restrict__ g2_wl, const float* __restrict__ g2_wr,
           const float* __restrict__ g2_att, const float* __restrict__ g2_b,
           const float* __restrict__ g3_wl, const float* __restrict__ g3_wr,
           const float* __restrict__ g3_att, const float* __restrict__ g3_b,
           const float* __restrict__ g4_wl, const float* __restrict__ g4_wr,
           const float* __restrict__ g4_att, const float* __restrict__ g4_b,
           const float* __restrict__ lab_w, const float* __restrict__ lab_b,
           const float* __restrict__ val_w, const float* __restrict__ val_b,
           const float* __restrict__ skip_w, const float* __restrict__ skip_b,
           float* __restrict__ out)
{
    extern __shared__ unsigned char smraw[];
    SM& S = *reinterpret_cast<SM*>(smraw);
    const int T = threadIdx.x;

    // ---- stage weights ONCE per (persistent) block ----
    for (int i = T; i < HID * HID; i += NTH) {
        const int k = i >> 6, hh = i & 63;
        const int d = hh * PAD + k;
        S.w_enc2t[d] = enc_w2[i];
        S.wl2t[d] = g2_wl[i]; S.wr2t[d] = g2_wr[i];
        S.wl3t[d] = g3_wl[i]; S.wr3t[d] = g3_wr[i];
        S.wl4t[d] = g4_wl[i]; S.wr4t[d] = g4_wr[i];
    }
    for (int i = T; i < 5 * HID; i += NTH) S.w_enc1[i] = enc_w1[i];
    for (int i = T; i < 4 * HID; i += NTH) S.w_lab[i] = lab_w[i];
    for (int i = T; i < 3 * HID; i += NTH) { S.w_enc3[i] = enc_w3[i]; S.w_skip[i] = skip_w[i]; }
    if (T < HID) {
        const int i = T;
        S.b_enc1[i] = enc_b1[i]; S.b_enc2[i] = enc_b2[i];
        S.g_wl1[i] = g1_wl[i];   S.g_wr1[i] = g1_wr[i];
        S.att1[i] = g1_att[i];   S.gb1[i] = g1_b[i];
        S.att2[i] = g2_att[i];   S.gb2[i] = g2_b[i];
        S.att3[i] = g3_att[i];   S.gb3[i] = g3_b[i];
        S.att4[i] = g4_att[i];   S.gb4[i] = g4_b[i];
        S.b_skip[i] = skip_b[i]; S.w_val[i] = val_w[i];
    } else if (T >= 64 && T < 67) {
        S.b_enc3[T - 64] = enc_b3[T - 64];
    } else if (T >= 68 && T < 72) {
        S.b_lab[T - 68] = lab_b[T - 68];
    } else if (T == 72) {
        S.b_val[0] = val_b[0];
    }
    __syncthreads();

    const int sb  = T / TPG;
    const int tid = T - sb * TPG;   // 0..127
    SubS& s = S.sub[sb];
    const int h  = tid & 63;        // mapping A (attn/agg/proj/heads)
    const int gg = tid >> 6;        // 0 or 1
    const int nb = gg * 6;
    const int hc = tid >> 1;        // mapping B (pair-shared GEMMs): column
    const int rb = (tid & 1) * 6;   //   row base (even: 0-5, odd: 6-11)

    for (int it = 0; it < ITERS; ++it) {
        const int b = (it * GRIDP + blockIdx.x) * NSUB + sb;
        const bool active = (b < NB);

        // ---- input + passthrough; reset pair counter ----
        if (tid == 127) s.pcnt = 0;
        if (active && tid < 60) {
            float v = batch[(size_t)b * 60 + tid];
            s.binp[tid] = v;
            int n = tid / 5, c = tid - n * 5;
            if (c < 4) out[O1 + (size_t)b * 48 + n * 4 + c] = v;
            else       out[O2 + (size_t)b * 12 + n] = v;
        }
        barsub(sb);

        // ---- encoder layer 1 (K=5) -> xA ----
        {
            float a[6];
            const float bv = S.b_enc1[h];
#pragma unroll
            for (int r = 0; r < 6; ++r) a[r] = bv;
#pragma unroll
            for (int k = 0; k < 5; ++k) {
                float w = S.w_enc1[k * HID + h];
#pragma unroll
                for (int r = 0; r < 6; ++r)
                    a[r] = fmaf(s.binp[(nb + r) * 5 + k], w, a[r]);
            }
#pragma unroll
            for (int r = 0; r < 6; ++r) s.xA[(nb + r) * APAD + h] = fmaxf(a[r], 0.f);
        }
        barsub(sb);

        // ---- encoder layer 2 -> xC (pair-shared) ----
        gemm64_relu6p(s.xA, S.w_enc2t, S.b_enc2, s.xC, hc, rb);
        barsub(sb);

        // ---- latent (64->3), k-split across lane pairs; 72 writers ----
        {
            const int t    = tid >> 1;
            const int half = tid & 1;
            const int tt   = (t < 36) ? t : 0;
            const int n    = tt / 3, c = tt - n * 3;
            float a = 0.f;
#pragma unroll
            for (int kk = 0; kk < 32; ++kk) {
                const int k = half * 32 + kk;
                a = fmaf(s.xC[n * APAD + k], S.w_enc3[k * 3 + c], a);
            }
            a += __shfl_xor_sync(0xFFFFFFFFu, a, 1);
            if (t < 36 && half == 0) {
                a += S.b_enc3[c];
                s.latent[n * 4 + c] = a;
                if (active) out[OT + (size_t)b * 36 + n * 3 + c] = a;
            }
        }
        barsub(sb);

        // ---- adjacency -> compacted pair list; zero e; skip(reg); GAT1 proj ----
        s.e[tid] = 0.0f;
        if (tid < 16) s.e[128 + tid] = 0.0f;
        {
            int adj0 = gabriel_adj(s, tid);
            if (adj0) {
                int k = atomicAdd(&s.pcnt, 1);
                s.plist[k] = (short)tid;
            }
            if (tid < 16) {
                int adj1 = gabriel_adj(s, tid + 128);
                if (adj1) {
                    int k = atomicAdd(&s.pcnt, 1);
                    s.plist[k] = (short)(tid + 128);
                }
            }
        }
        float skipreg[6];
        {
            const float bv = S.b_skip[h];
#pragma unroll
            for (int r = 0; r < 6; ++r) skipreg[r] = bv;
#pragma unroll
            for (int c = 0; c < 3; ++c) {
                float w = S.w_skip[c * HID + h];
#pragma unroll
                for (int r = 0; r < 6; ++r)
                    skipreg[r] = fmaf(s.latent[(nb + r) * 4 + c], w, skipreg[r]);
            }
        }
        {
            float wl = S.g_wl1[h], wr = S.g_wr1[h];
#pragma unroll
            for (int r = 0; r < 6; ++r) {
                float v = s.latent[(nb + r) * 4 + 2];
                s.xl[(nb + r) * PAD + h] = v * wl;
                s.xr[(nb + r) * PAD + h] = v * wr;
            }
        }
        barsub(sb);

        // ---- GAT 1 -> xA (x1) ----
        gat_scores(s, S.att1, tid);
        barsub(sb);
        gat_agg6(s, S.gb1, s.xA, h, gg, skipreg, 0);
        barsub(sb);

        // ---- GAT 2 -> xC (x2) ----
        dual_gemm6p(s.xA, S.wl2t, S.wr2t, s.xl, s.xr, hc, rb);
        barsub(sb);
        gat_scores(s, S.att2, tid);
        barsub(sb);
        gat_agg6(s, S.gb2, s.xC, h, gg, skipreg, 0);
        barsub(sb);

        // ---- GAT 3 -> xA (x3) ----
        dual_gemm6p(s.xC, S.wl3t, S.wr3t, s.xl, s.xr, hc, rb);
        barsub(sb);
        gat_scores(s, S.att3, tid);
        barsub(sb);
        gat_agg6(s, S.gb3, s.xA, h, gg, skipreg, 1);
        barsub(sb);

        // ---- GAT 4 projections (reads xC = x2) + logits head (reads xA = x3) ----
        dual_gemm6p(s.xC, S.wl4t, S.wr4t, s.xl, s.xr, hc, rb);
        {
            const int t    = tid >> 1;
            const int half = tid & 1;
            if (t < 48) {   // warps 0-2 fully active; warp 3 skips (warp-aligned)
                const int n = t / 4, c = t - n * 4;
                float a = 0.f;
#pragma unroll
                for (int kk = 0; kk < 32; ++kk) {
                    const int k = half * 32 + kk;
                    a = fmaf(s.xA[n * APAD + k], S.w_lab[k * 4 + c], a);
                }
                a += __shfl_xor_sync(0xFFFFFFFFu, a, 1);
                if (active && half == 0)
                    out[OL + (size_t)b * 48 + n * 4 + c] = a + S.b_lab[c];
            }
        }
        barsub(sb);

        // ---- GAT 4 -> xA (x4) ----
        gat_scores(s, S.att4, tid);
        barsub(sb);
        gat_agg6(s, S.gb4, s.xA, h, gg, skipreg, 1);
        barsub(sb);

        // ---- values head (k-split, warp 0 only) ----
        if (tid < 32) {
            const int t    = tid >> 1;
            const int half = tid & 1;
            const int n    = (t < NN) ? t : 0;
            float a = 0.f;
#pragma unroll
            for (int kk = 0; kk < 32; ++kk) {
                const int k = half * 32 + kk;
                a = fmaf(s.xA[n * APAD + k], S.w_val[k], a);
            }
            a += __shfl_xor_sync(0xFFFFFFFFu, a, 1);
            if (active && t < NN && half == 0)
                out[OV + (size_t)b * 12 + n] = a + S.b_val[0];
        }
        // loop: next iteration's first barsub orders xA reuse
    }
}

} // anonymous namespace

extern "C" void kernel_launch(void* const* d_in, const int* in_sizes, int n_in,
                              void* d_out, int out_size)
{
    const float* p[29];
    for (int i = 0; i < 29; ++i) p[i] = (const float*)d_in[i];
    float* out = (float*)d_out;

    cudaFuncSetAttribute(gae_kernel, cudaFuncAttributeMaxDynamicSharedMemorySize,
                         (int)sizeof(SM));

    gae_kernel<<<GRIDP, NTH, sizeof(SM)>>>(
        p[0],
        p[1], p[2], p[3], p[4], p[5], p[6],
        p[7], p[8], p[9], p[10],
        p[11], p[12], p[13], p[14],
        p[15], p[16], p[17], p[18],
        p[19], p[20], p[21], p[22],
        p[23], p[24], p[25], p[26], p[27], p[28],
        out);
}